// round 9
// baseline (speedup 1.0000x reference)
#include <cuda_runtime.h>
#include <cuda_bf16.h>
#include <cstdint>
#include <math.h>

#define NPTS    524288
#define NGRIDS  64
#define GVOX    262144      /* 64^3 */
#define PE_L    6
#define NBUCK   4096
#define THREADS 512
#define PTS_CTA 512

// x-duplicated channel-interleaved volumes (256 MB)
__device__ float4 g_dupx[NGRIDS * GVOX];
__device__ int    g_hist[NBUCK];
__device__ int    g_off[NBUCK];
__device__ int    g_perm[NPTS];

// ---------------- packed f32x2 helpers ----------------
__device__ __forceinline__ void fma2(unsigned long long& d,
                                     unsigned long long a,
                                     unsigned long long b) {
    asm("fma.rn.f32x2 %0, %1, %2, %0;" : "+l"(d) : "l"(a), "l"(b));
}
__device__ __forceinline__ unsigned long long bcast2(float f) {
    unsigned long long r;
    asm("mov.b64 %0, {%1, %2};" : "=l"(r) : "f"(f), "f"(f));
    return r;
}
__device__ __forceinline__ float2 unpack2(unsigned long long v) {
    float2 f;
    asm("mov.b64 {%0, %1}, %2;" : "=f"(f.x), "=f"(f.y) : "l"(v));
    return f;
}
__device__ __forceinline__ unsigned long long pack2(float a, float b) {
    unsigned long long r;
    asm("mov.b64 %0, {%1, %2};" : "=l"(r) : "f"(a), "f"(b));
    return r;
}
__device__ __forceinline__ void accum_row_s(unsigned long long* acc,
                                            const float* row, float f) {
    unsigned long long ff = bcast2(f);
    const ulonglong2* r2 = reinterpret_cast<const ulonglong2*>(row);
#pragma unroll
    for (int i = 0; i < 16; i++) {
        ulonglong2 w = r2[i];
        fma2(acc[2 * i], ff, w.x);
        fma2(acc[2 * i + 1], ff, w.y);
    }
}
__device__ __forceinline__ void mma16816(float* c, const uint32_t* a,
                                         uint32_t b0, uint32_t b1) {
    asm volatile(
        "mma.sync.aligned.m16n8k16.row.col.f32.bf16.bf16.f32 "
        "{%0,%1,%2,%3}, {%4,%5,%6,%7}, {%8,%9}, {%0,%1,%2,%3};"
        : "+f"(c[0]), "+f"(c[1]), "+f"(c[2]), "+f"(c[3])
        : "r"(a[0]), "r"(a[1]), "r"(a[2]), "r"(a[3]), "r"(b0), "r"(b1));
}
// packed bf16 hi/lo in one u32:  (lo16 << 16) | hi16
__device__ __forceinline__ uint32_t pack_hl(float v) {
    __nv_bfloat16 h = __float2bfloat16(v);
    __nv_bfloat16 l = __float2bfloat16(v - __bfloat162float(h));
    return ((uint32_t)__bfloat16_as_ushort(l) << 16) | __bfloat16_as_ushort(h);
}
__device__ __forceinline__ float snakef(float h) {
    float s = __sinf(h);
    return fmaf(0.5f, h, s * s);
}
__device__ __forceinline__ int bucket_key(float px, float py, float pz) {
    int qx = min(max((int)((px + 1.f) * 8.f), 0), 15);
    int qy = min(max((int)((py + 1.f) * 8.f), 0), 15);
    int qz = min(max((int)((pz + 1.f) * 8.f), 0), 15);
    return (qx << 8) | (qy << 4) | qz;
}

// ---------------- repack + sort pipeline (unchanged from R8) ----------------
__global__ void repack_dup(const float* __restrict__ fg) {
    int idx = blockIdx.x * blockDim.x + threadIdx.x;
    int g = idx >> 16;
    int v4 = (idx & 65535) << 2;
    const float* f0p = fg + (size_t)(2 * g) * GVOX;
    const float* f1p = fg + (size_t)(2 * g + 1) * GVOX;
    float4 a = *(const float4*)(f0p + v4);
    float4 b = *(const float4*)(f1p + v4);
    float a4, b4;
    if ((v4 & 63) == 60) { a4 = a.w; b4 = b.w; }
    else                 { a4 = f0p[v4 + 4]; b4 = f1p[v4 + 4]; }
    float4* o = g_dupx + ((size_t)g << 18) + v4;
    o[0] = make_float4(a.x, b.x, a.y, b.y);
    o[1] = make_float4(a.y, b.y, a.z, b.z);
    o[2] = make_float4(a.z, b.z, a.w, b.w);
    o[3] = make_float4(a.w, b.w, a4, b4);
}
__global__ void zero_hist() {
    g_hist[blockIdx.x * blockDim.x + threadIdx.x] = 0;
}
__global__ void hist_kernel(const float* __restrict__ x) {
    int pt = blockIdx.x * blockDim.x + threadIdx.x;
    int k = bucket_key(x[3 * pt], x[3 * pt + 1], x[3 * pt + 2]);
    atomicAdd(&g_hist[k], 1);
}
__global__ void scan_hist() {
    __shared__ int s[1024];
    int t = threadIdx.x;
    int base = t * 4;
    int a0 = g_hist[base], a1 = g_hist[base + 1], a2 = g_hist[base + 2],
        a3 = g_hist[base + 3];
    int sum = a0 + a1 + a2 + a3;
    s[t] = sum;
    __syncthreads();
    for (int d = 1; d < 1024; d <<= 1) {
        int v = (t >= d) ? s[t - d] : 0;
        __syncthreads();
        s[t] += v;
        __syncthreads();
    }
    int excl = s[t] - sum;
    g_off[base] = excl;
    g_off[base + 1] = excl + a0;
    g_off[base + 2] = excl + a0 + a1;
    g_off[base + 3] = excl + a0 + a1 + a2;
}
__global__ void scatter_kernel(const float* __restrict__ x) {
    int pt = blockIdx.x * blockDim.x + threadIdx.x;
    int k = bucket_key(x[3 * pt], x[3 * pt + 1], x[3 * pt + 2]);
    int pos = atomicAdd(&g_off[k], 1);
    g_perm[pos] = pt;
}

// ---------------- smem layout (bytes) ----------------
#define SM_PE   0                         /* 36*64 f32 = 9216            */
#define SM_W0G  9216                      /* 64*132 f32 = 33792          */
#define SM_GP   43008                     /* 64*8 f32 = 2048             */
#define SM_AUX  45056                     /* b0[64] b1[64] w2[64] = 768  */
#define SM_W1P  45888                     /* 64*68 u32 = 17408           */
#define SM_H0   63360                     /* 512*68 u32 = 139264         */
#define SMEM_TOTAL 202624

__global__ void __launch_bounds__(THREADS, 1)
amrsrn_main(const float* __restrict__ x,
            const float* __restrict__ gscale,
            const float* __restrict__ gtrans,
            const float* __restrict__ W0,
            const float* __restrict__ b0,
            const float* __restrict__ W1,
            const float* __restrict__ b1,
            const float* __restrict__ W2,
            const float* __restrict__ b2,
            float* __restrict__ out) {
    extern __shared__ char smem[];
    float* smf = (float*)smem;
    float* auxf = (float*)(smem + SM_AUX);
    uint32_t* W1P = (uint32_t*)(smem + SM_W1P);
    uint32_t* H0 = (uint32_t*)(smem + SM_H0);
    const int tid = threadIdx.x;

    // ---- stage weights ----
    for (int i = tid; i < 36 * 64; i += THREADS)
        smf[SM_PE / 4 + i] = W0[i];
    for (int i = tid; i < 64 * 128; i += THREADS) {
        int g = i >> 7, j = i & 127;
        int row = 36 + 2 * g + (j >> 6);
        smf[SM_W0G / 4 + g * 132 + j] = W0[row * 64 + (j & 63)];
    }
    for (int i = tid; i < 64 * 64; i += THREADS) {     // W1 packed hi/lo [n][k]
        int n = i & 63, k = i >> 6;
        W1P[n * 68 + k] = pack_hl(W1[k * 64 + n]);
    }
    for (int i = tid; i < 64; i += THREADS) {
        auxf[i] = b0[i];
        auxf[64 + i] = b1[i];
        auxf[128 + i] = W2[i];
    }
    for (int i = tid; i < 64; i += THREADS) {
        smf[SM_GP / 4 + i * 8 + 0] = gscale[3 * i + 0];
        smf[SM_GP / 4 + i * 8 + 1] = gscale[3 * i + 1];
        smf[SM_GP / 4 + i * 8 + 2] = gscale[3 * i + 2];
        smf[SM_GP / 4 + i * 8 + 3] = gtrans[3 * i + 0];
        smf[SM_GP / 4 + i * 8 + 4] = gtrans[3 * i + 1];
        smf[SM_GP / 4 + i * 8 + 5] = gtrans[3 * i + 2];
        smf[SM_GP / 4 + i * 8 + 6] = 0.f;
        smf[SM_GP / 4 + i * 8 + 7] = 0.f;
    }
    __syncthreads();

    const int pt = g_perm[blockIdx.x * PTS_CTA + tid];
    const float px = __ldg(&x[3 * pt + 0]);
    const float py = __ldg(&x[3 * pt + 1]);
    const float pz = __ldg(&x[3 * pt + 2]);
    const float xyz[3] = {px, py, pz};
    const float4* gp4 = (const float4*)(smem + SM_GP);

    // ---- h0 accumulators (32 packed f32x2), init = b0 ----
    unsigned long long acc[32];
    const unsigned long long* pb0 = (const unsigned long long*)&auxf[0];
#pragma unroll
    for (int i = 0; i < 32; i++) acc[i] = pb0[i];

    // ---- PE via double-angle recurrence (smem broadcast rows) ----
#pragma unroll
    for (int d = 0; d < 3; d++) {
        float s, c;
        sincosf(xyz[d] * 3.14159265358979323846f, &s, &c);
#pragma unroll
        for (int l = 0; l < PE_L; l++) {
            accum_row_s(acc, &smf[SM_PE / 4 + (l * 3 + d) * 64], s);
            accum_row_s(acc, &smf[SM_PE / 4 + (18 + l * 3 + d) * 64], c);
            float s2 = 2.f * s * c;
            float c2 = fmaf(-2.f * s, s, 1.f);
            s = s2;
            c = c2;
        }
    }

    // ---- validity mask ----
    unsigned long long mask = 0ull;
#pragma unroll 1
    for (int g = 0; g < 64; g++) {
        float4 p1 = gp4[g * 2];
        float4 p2 = gp4[g * 2 + 1];
        float ix = fmaf(fmaf(px, p1.x, p1.w), 31.5f, 31.5f);
        float iy = fmaf(fmaf(py, p1.y, p2.x), 31.5f, 31.5f);
        float iz = fmaf(fmaf(pz, p1.z, p2.y), 31.5f, 31.5f);
        if (ix > -1.f && ix < 64.f && iy > -1.f && iy < 64.f && iz > -1.f &&
            iz < 64.f)
            mask |= 1ull << g;
    }

    // ---- compacted sparse gather + accumulation ----
    while (mask) {
        int g = __ffsll((long long)mask) - 1;
        mask &= mask - 1;
        float4 p1 = gp4[g * 2];
        float4 p2 = gp4[g * 2 + 1];
        float ix = fmaf(fmaf(px, p1.x, p1.w), 31.5f, 31.5f);
        float iy = fmaf(fmaf(py, p1.y, p2.x), 31.5f, 31.5f);
        float iz = fmaf(fmaf(pz, p1.z, p2.y), 31.5f, 31.5f);
        float fx = floorf(ix), fy = floorf(iy), fz = floorf(iz);
        int X0 = (int)fx, Y0 = (int)fy, Z0 = (int)fz;
        float wx1 = ix - fx, wy1 = iy - fy, wz1 = iz - fz;
        float wx0 = 1.f - wx1, wy0 = 1.f - wy1, wz0 = 1.f - wz1;
        int bx = X0;
        float wa = wx0, wb = wx1;
        if (X0 < 0)        { bx = 0; wa = wx1; wb = 0.f; }
        else if (X0 >= 63) { wb = 0.f; }
        if (Y0 < 0)   wy0 = 0.f;
        if (Y0 >= 63) wy1 = 0.f;
        if (Z0 < 0)   wz0 = 0.f;
        if (Z0 >= 63) wz1 = 0.f;
        int y0c = max(Y0, 0), y1c = min(Y0 + 1, 63);
        int z0c = max(Z0, 0), z1c = min(Z0 + 1, 63);

        const float4* vol = g_dupx + ((size_t)g << 18);
        float4 q00 = __ldg(&vol[(z0c << 12) + (y0c << 6) + bx]);
        float4 q01 = __ldg(&vol[(z0c << 12) + (y1c << 6) + bx]);
        float4 q10 = __ldg(&vol[(z1c << 12) + (y0c << 6) + bx]);
        float4 q11 = __ldg(&vol[(z1c << 12) + (y1c << 6) + bx]);

        float w00 = wz0 * wy0, w01 = wz0 * wy1;
        float w10 = wz1 * wy0, w11 = wz1 * wy1;

        float r00 = fmaf(wb, q00.z, wa * q00.x);
        float r01 = fmaf(wb, q01.z, wa * q01.x);
        float r10 = fmaf(wb, q10.z, wa * q10.x);
        float r11 = fmaf(wb, q11.z, wa * q11.x);
        float f0 = w00 * r00;
        f0 = fmaf(w01, r01, f0);
        f0 = fmaf(w10, r10, f0);
        f0 = fmaf(w11, r11, f0);

        float s00 = fmaf(wb, q00.w, wa * q00.y);
        float s01 = fmaf(wb, q01.w, wa * q01.y);
        float s10 = fmaf(wb, q10.w, wa * q10.y);
        float s11 = fmaf(wb, q11.w, wa * q11.y);
        float f1 = w00 * s00;
        f1 = fmaf(w01, s01, f1);
        f1 = fmaf(w10, s10, f1);
        f1 = fmaf(w11, s11, f1);

        const float* wrow = &smf[SM_W0G / 4 + g * 132];
        accum_row_s(acc, wrow, f0);
        accum_row_s(acc, wrow + 64, f1);
    }

    // ---- snake on h0, pack hi/lo, store to smem (16 STS.128) ----
#pragma unroll
    for (int i = 0; i < 16; i++) {
        float2 va = unpack2(acc[2 * i]);
        float2 vb = unpack2(acc[2 * i + 1]);
        float sa0 = __sinf(va.x), sa1 = __sinf(va.y);
        float sb0 = __sinf(vb.x), sb1 = __sinf(vb.y);
        uint4 u;
        u.x = pack_hl(fmaf(0.5f, va.x, sa0 * sa0));
        u.y = pack_hl(fmaf(0.5f, va.y, sa1 * sa1));
        u.z = pack_hl(fmaf(0.5f, vb.x, sb0 * sb0));
        u.w = pack_hl(fmaf(0.5f, vb.y, sb1 * sb1));
        *(uint4*)&H0[tid * 68 + 4 * i] = u;
    }
    __syncwarp();

    // ---- layer 1 as warp-level HMMA (3-term bf16 hi/lo split) ----
    const int lane = tid & 31;
    const int gid = lane >> 2;
    const int tid4 = lane & 3;
    const int p0w = (tid >> 5) * 32;   // warp's first slot in CTA

    float acc1[2][8][4];
#pragma unroll
    for (int mt = 0; mt < 2; mt++)
#pragma unroll
        for (int nt = 0; nt < 8; nt++)
#pragma unroll
            for (int j = 0; j < 4; j++) acc1[mt][nt][j] = 0.f;

#pragma unroll
    for (int kt = 0; kt < 4; kt++) {
        const int k0 = kt * 16 + tid4 * 2;
        uint32_t aH[2][4], aL[2][4];
#pragma unroll
        for (int mt = 0; mt < 2; mt++) {
            int r = p0w + mt * 16 + gid;
            uint2 u0 = *(const uint2*)&H0[r * 68 + k0];
            uint2 u1 = *(const uint2*)&H0[(r + 8) * 68 + k0];
            uint2 u2 = *(const uint2*)&H0[r * 68 + k0 + 8];
            uint2 u3 = *(const uint2*)&H0[(r + 8) * 68 + k0 + 8];
            aH[mt][0] = __byte_perm(u0.x, u0.y, 0x5410);
            aL[mt][0] = __byte_perm(u0.x, u0.y, 0x7632);
            aH[mt][1] = __byte_perm(u1.x, u1.y, 0x5410);
            aL[mt][1] = __byte_perm(u1.x, u1.y, 0x7632);
            aH[mt][2] = __byte_perm(u2.x, u2.y, 0x5410);
            aL[mt][2] = __byte_perm(u2.x, u2.y, 0x7632);
            aH[mt][3] = __byte_perm(u3.x, u3.y, 0x5410);
            aL[mt][3] = __byte_perm(u3.x, u3.y, 0x7632);
        }
#pragma unroll
        for (int nt = 0; nt < 8; nt++) {
            int rB = nt * 8 + gid;
            uint2 w0 = *(const uint2*)&W1P[rB * 68 + k0];
            uint2 w1 = *(const uint2*)&W1P[rB * 68 + k0 + 8];
            uint32_t bh0 = __byte_perm(w0.x, w0.y, 0x5410);
            uint32_t bl0 = __byte_perm(w0.x, w0.y, 0x7632);
            uint32_t bh1 = __byte_perm(w1.x, w1.y, 0x5410);
            uint32_t bl1 = __byte_perm(w1.x, w1.y, 0x7632);
#pragma unroll
            for (int mt = 0; mt < 2; mt++) {
                mma16816(acc1[mt][nt], aH[mt], bh0, bh1);
                mma16816(acc1[mt][nt], aL[mt], bh0, bh1);
                mma16816(acc1[mt][nt], aH[mt], bl0, bl1);
            }
        }
    }

    // ---- epilogue: bias + snake + W2 dot + quad reduce + scatter out ----
    const float b2v = __ldg(b2);
#pragma unroll
    for (int mt = 0; mt < 2; mt++) {
        float pr0 = 0.f, pr8 = 0.f;
#pragma unroll
        for (int nt = 0; nt < 8; nt++) {
            int cb = nt * 8 + tid4 * 2;
            float b1a = auxf[64 + cb], b1b = auxf[64 + cb + 1];
            float w2a = auxf[128 + cb], w2b = auxf[128 + cb + 1];
            pr0 = fmaf(snakef(acc1[mt][nt][0] + b1a), w2a, pr0);
            pr0 = fmaf(snakef(acc1[mt][nt][1] + b1b), w2b, pr0);
            pr8 = fmaf(snakef(acc1[mt][nt][2] + b1a), w2a, pr8);
            pr8 = fmaf(snakef(acc1[mt][nt][3] + b1b), w2b, pr8);
        }
        pr0 += __shfl_xor_sync(0xffffffffu, pr0, 1);
        pr0 += __shfl_xor_sync(0xffffffffu, pr0, 2);
        pr8 += __shfl_xor_sync(0xffffffffu, pr8, 1);
        pr8 += __shfl_xor_sync(0xffffffffu, pr8, 2);
        int ptA = __shfl_sync(0xffffffffu, pt, mt * 16 + gid);
        int ptB = __shfl_sync(0xffffffffu, pt, mt * 16 + gid + 8);
        if (tid4 == 0) {
            out[ptA] = pr0 + b2v;
            out[ptB] = pr8 + b2v;
        }
    }
}

extern "C" void kernel_launch(void* const* d_in, const int* in_sizes, int n_in,
                              void* d_out, int out_size) {
    const float* x      = (const float*)d_in[0];
    const float* gsc    = (const float*)d_in[1];
    const float* gtr    = (const float*)d_in[2];
    const float* fgrids = (const float*)d_in[3];
    const float* W0     = (const float*)d_in[4];
    const float* b0     = (const float*)d_in[5];
    const float* W1     = (const float*)d_in[6];
    const float* b1     = (const float*)d_in[7];
    const float* W2     = (const float*)d_in[8];
    const float* b2     = (const float*)d_in[9];
    float* out          = (float*)d_out;

    cudaFuncSetAttribute(amrsrn_main,
                         cudaFuncAttributeMaxDynamicSharedMemorySize,
                         SMEM_TOTAL);

    repack_dup<<<(NGRIDS * GVOX / 4) / 256, 256>>>(fgrids);
    zero_hist<<<16, 256>>>();
    hist_kernel<<<NPTS / 256, 256>>>(x);
    scan_hist<<<1, 1024>>>();
    scatter_kernel<<<NPTS / 256, 256>>>(x);
    amrsrn_main<<<NPTS / PTS_CTA, THREADS, SMEM_TOTAL>>>(x, gsc, gtr, W0, b0,
                                                         W1, b1, W2, b2, out);
}